// round 4
// baseline (speedup 1.0000x reference)
#include <cuda_runtime.h>
#include <cuda_bf16.h>

// SSIM fused single-kernel, f32x2-packed, occupancy-tuned (4 blocks/SM).
// X,Y: [64,1,320,320] f32; window [1,1,7,7] rank-1 Gaussian. out = 1 - mean(ssim).
//
// Tile 64 wide x 20 tall; the two 32-wide halves packed into f32x2 pairs.
// Streams reduced to 4 (sx, sy, sxx+syy, sxy) since vertical conv is linear.

typedef unsigned long long u64;

#define IMG_H 320
#define IMG_W 320
#define N_IMG 64
#define TILE_W 64
#define TILE_H 20
#define HALO 3
#define IN_R   26             // TILE_H + 6
#define IN_PC  38             // pair-columns incl. halo
#define IN_ST  38             // sX/sY row stride (u64) — LDS.128 conflict-free
#define HB_RST 133            // hbuf row stride (u64), odd -> conflict-free u64 ops
#define HB_SST 33             // stream offset within a row
#define SMEM_U64 (2 * IN_R * IN_ST + IN_R * HB_RST)   // 1976 + 3458 = 5434 u64
#define GRID_X (IMG_W / TILE_W)     // 5
#define GRID_Y (IMG_H / TILE_H)     // 16
#define NBLOCKS (GRID_X * GRID_Y * N_IMG)   // 5120

#define C1_CONST 0.0004f
#define C2_CONST 0.0036f
#define COV_NORM_CONST (49.0f / 48.0f)

__device__ float g_part[NBLOCKS];
__device__ unsigned g_ticket;   // wraps back to 0 via atomicInc -> graph-replay safe

__device__ __forceinline__ u64 pack2(float lo, float hi) {
    u64 d; asm("mov.b64 %0, {%1,%2};" : "=l"(d) : "f"(lo), "f"(hi)); return d;
}
__device__ __forceinline__ void unpack2(u64 v, float& lo, float& hi) {
    asm("mov.b64 {%0,%1}, %2;" : "=f"(lo), "=f"(hi) : "l"(v));
}
__device__ __forceinline__ u64 fma2(u64 a, u64 b, u64 c) {
    u64 d; asm("fma.rn.f32x2 %0, %1, %2, %3;" : "=l"(d) : "l"(a), "l"(b), "l"(c)); return d;
}
__device__ __forceinline__ u64 mul2(u64 a, u64 b) {
    u64 d; asm("mul.rn.f32x2 %0, %1, %2;" : "=l"(d) : "l"(a), "l"(b)); return d;
}
__device__ __forceinline__ u64 add2(u64 a, u64 b) {
    u64 d; asm("add.rn.f32x2 %0, %1, %2;" : "=l"(d) : "l"(a), "l"(b)); return d;
}

__global__ __launch_bounds__(256, 4)
void ssim_kernel(const float* __restrict__ X, const float* __restrict__ Y,
                 const float* __restrict__ W, float* __restrict__ out) {
    extern __shared__ u64 sm[];
    u64* sX = sm;
    u64* sY = sm + IN_R * IN_ST;
    u64* sH = sm + 2 * IN_R * IN_ST;   // [26 rows][4 streams x 33 + 1 pad]
    __shared__ float warp_sums[8];
    __shared__ int is_last;

    const int tid = threadIdx.x;
    const int bx = blockIdx.x * TILE_W;
    const int by = blockIdx.y * TILE_H;
    const int n  = blockIdx.z;

    // Separable weights from rank-1 window: u_i = W[i][3]/sqrt(W[3][3])
    u64 wp[7];
    {
        float wc = sqrtf(W[3 * 7 + 3]);
        #pragma unroll
        for (int i = 0; i < 7; i++) {
            float w = W[i * 7 + 3] / wc;
            wp[i] = pack2(w, w);
        }
    }

    const float* Xn = X + (size_t)n * IMG_H * IMG_W;
    const float* Yn = Y + (size_t)n * IMG_H * IMG_W;

    // ---- Phase 1: load 26 rows x 38 pair-cols; pair p = (col p-3, col p+29) ----
    #pragma unroll
    for (int ii = 0; ii < 4; ii++) {
        int i = tid + ii * 256;
        if (i < IN_R * IN_PC) {
            int r = i / IN_PC;
            int c = i - r * IN_PC;
            int gy = by + r - HALO;
            int cl = bx + c - HALO;
            int cr = cl + 32;
            float xl = 0.f, xr = 0.f, yl = 0.f, yr = 0.f;
            if ((unsigned)gy < (unsigned)IMG_H) {
                const float* xrow = Xn + gy * IMG_W;
                const float* yrow = Yn + gy * IMG_W;
                if ((unsigned)cl < (unsigned)IMG_W) { xl = xrow[cl]; yl = yrow[cl]; }
                if ((unsigned)cr < (unsigned)IMG_W) { xr = xrow[cr]; yr = yrow[cr]; }
            }
            sX[r * IN_ST + c] = pack2(xl, xr);
            sY[r * IN_ST + c] = pack2(yl, yr);
        }
    }
    __syncthreads();

    // ---- Phase 2: horizontal conv, 26 rows x 8 groups of 4 pair-cols ----
    // Thread (r = tid&31 if < 26, cg = tid>>5). Two j=2 sub-windows (8 cols each)
    // keep live register state <= 32 for the windows.
    {
        const int r  = tid & 31;
        const int cg = tid >> 5;
        if (r < IN_R) {
            const int c0 = cg * 4;
            u64* hrow = sH + r * HB_RST;
            #pragma unroll
            for (int half = 0; half < 2; half++) {
                const u64* px = sX + r * IN_ST + c0 + 2 * half;
                const u64* py = sY + r * IN_ST + c0 + 2 * half;
                u64 xw[8], yw[8];
                #pragma unroll
                for (int k = 0; k < 4; k++) {
                    ulonglong2 vx = *(const ulonglong2*)(px + 2 * k);
                    ulonglong2 vy = *(const ulonglong2*)(py + 2 * k);
                    xw[2 * k] = vx.x; xw[2 * k + 1] = vx.y;
                    yw[2 * k] = vy.x; yw[2 * k + 1] = vy.y;
                }
                #pragma unroll
                for (int j = 0; j < 2; j++) {
                    u64 sx = 0, sy = 0, sxx = 0, syy = 0, sxy = 0;
                    #pragma unroll
                    for (int k = 0; k < 7; k++) {
                        u64 x = xw[j + k], y = yw[j + k], w = wp[k];
                        sx = fma2(x, w, sx);
                        sy = fma2(y, w, sy);
                        u64 wx = mul2(x, w);
                        u64 wy = mul2(y, w);
                        sxx = fma2(wx, x, sxx);
                        syy = fma2(wy, y, syy);
                        sxy = fma2(wx, y, sxy);
                    }
                    int c = c0 + 2 * half + j;
                    hrow[0 * HB_SST + c] = sx;
                    hrow[1 * HB_SST + c] = sy;
                    hrow[2 * HB_SST + c] = add2(sxx, syy);
                    hrow[3 * HB_SST + c] = sxy;
                }
            }
        }
    }
    __syncthreads();

    // ---- Phase 3: vertical conv + SSIM. 320 tasks (2 output rows x 32 cols each):
    // round 1 = 256 tasks (g=0..7), round 2 = 64 tasks (g=8,9; tid<64). ----
    float facc = 0.f;
    #pragma unroll
    for (int rnd = 0; rnd < 2; rnd++) {
        int g = (rnd == 0) ? (tid >> 5) : (8 + (tid >> 5));
        bool active = (rnd == 0) || (tid < 64);
        if (active) {
            const int c  = tid & 31;
            const int r0 = 2 * g;
            const u64* hc = sH + r0 * HB_RST + c;

            u64 mux[2], muy[2], s23[2], sxyv[2];
            #pragma unroll
            for (int s = 0; s < 4; s++) {
                u64 vw[8];
                #pragma unroll
                for (int i = 0; i < 8; i++)
                    vw[i] = hc[i * HB_RST + s * HB_SST];
                #pragma unroll
                for (int j = 0; j < 2; j++) {
                    u64 acc = 0;
                    #pragma unroll
                    for (int k = 0; k < 7; k++)
                        acc = fma2(vw[j + k], wp[k], acc);
                    if (s == 0) mux[j] = acc;
                    else if (s == 1) muy[j] = acc;
                    else if (s == 2) s23[j] = acc;
                    else sxyv[j] = acc;
                }
            }

            const u64 C1p  = pack2(C1_CONST, C1_CONST);
            const u64 C2p  = pack2(C2_CONST, C2_CONST);
            const u64 covp = pack2(COV_NORM_CONST, COV_NORM_CONST);
            const u64 negp = pack2(-1.f, -1.f);
            const u64 twop = pack2(2.f, 2.f);

            #pragma unroll
            for (int j = 0; j < 2; j++) {
                u64 muxy = mul2(mux[j], muy[j]);
                u64 P    = fma2(mux[j], mux[j], mul2(muy[j], muy[j]));
                u64 ssum = mul2(fma2(P,    negp, s23[j]),  covp);
                u64 sxy  = mul2(fma2(muxy, negp, sxyv[j]), covp);
                u64 num = mul2(fma2(twop, muxy, C1p), fma2(twop, sxy, C2p));
                u64 den = mul2(add2(P, C1p), add2(ssum, C2p));
                float nl, nh, dl, dh;
                unpack2(num, nl, nh);
                unpack2(den, dl, dh);
                facc += __fdividef(nl, dl) + __fdividef(nh, dh);
            }
        }
    }

    // ---- Block reduction -> per-block float partial ----
    #pragma unroll
    for (int off = 16; off > 0; off >>= 1)
        facc += __shfl_down_sync(0xffffffffu, facc, off);
    if ((tid & 31) == 0) warp_sums[tid >> 5] = facc;
    __syncthreads();
    if (tid == 0) {
        float bs = 0.f;
        #pragma unroll
        for (int w = 0; w < 8; w++) bs += warp_sums[w];
        int bid = blockIdx.x + GRID_X * (blockIdx.y + GRID_Y * blockIdx.z);
        g_part[bid] = bs;
        __threadfence();
        unsigned ticket = atomicInc(&g_ticket, NBLOCKS - 1);
        is_last = (ticket == NBLOCKS - 1);
    }
    __syncthreads();

    // ---- Last block: deterministic double reduction ----
    if (is_last) {
        __shared__ double dsums[8];
        double s = 0.0;
        for (int i = tid; i < NBLOCKS; i += 256) s += (double)__ldcg(&g_part[i]);
        #pragma unroll
        for (int off = 16; off > 0; off >>= 1)
            s += __shfl_down_sync(0xffffffffu, s, off);
        if ((tid & 31) == 0) dsums[tid >> 5] = s;
        __syncthreads();
        if (tid == 0) {
            double t = 0.0;
            #pragma unroll
            for (int w = 0; w < 8; w++) t += dsums[w];
            double total = (double)N_IMG * IMG_H * IMG_W;
            out[0] = (float)(1.0 - t / total);
        }
    }
}

extern "C" void kernel_launch(void* const* d_in, const int* in_sizes, int n_in,
                              void* d_out, int out_size) {
    const float* X = (const float*)d_in[0];
    const float* Y = (const float*)d_in[1];
    const float* W = (const float*)d_in[2];
    float* out = (float*)d_out;

    size_t smem_bytes = (size_t)SMEM_U64 * sizeof(u64);
    cudaFuncSetAttribute(ssim_kernel, cudaFuncAttributeMaxDynamicSharedMemorySize,
                         (int)smem_bytes);

    dim3 grid(GRID_X, GRID_Y, N_IMG);
    ssim_kernel<<<grid, 256, smem_bytes>>>(X, Y, W, out);
}

// round 5
// speedup vs baseline: 1.1749x; 1.1749x over previous
#include <cuda_runtime.h>
#include <cuda_bf16.h>

// SSIM fused single-kernel, f32x2-packed. X,Y: [64,1,320,320] f32; 7x7 rank-1 window.
// out = 1 - mean(ssim_map).
// Tile 64x32 (pairs (c, c+32) packed in f32x2). 4 conv streams: sx, sy, sxx+syy, sxy.
// hbuf column-major [32 cols][162 u64] so vertical pass reads LDS.128 row-runs.

typedef unsigned long long u64;

#define IMG_H 320
#define IMG_W 320
#define N_IMG 64
#define TILE_W 64
#define TILE_H 32
#define HALO 3
#define IN_R   38             // TILE_H + 6
#define IN_PC  38             // pair-columns incl. halo
#define IN_ST  38             // sX/sY row stride (u64)
#define HB_SST 40             // stream stride within a column (38 rows + 2)
#define HB_COLST 162          // 4*40 + 2 pad: bank start 4c mod 32 -> conflict-free
#define SMEM_U64 (2 * IN_R * IN_ST + 32 * HB_COLST)   // 2888 + 5184 = 8072 u64
#define GRID_X (IMG_W / TILE_W)     // 5
#define GRID_Y (IMG_H / TILE_H)     // 10
#define NBLOCKS (GRID_X * GRID_Y * N_IMG)   // 3200

#define C1_CONST 0.0004f
#define C2_CONST 0.0036f
#define COV_NORM_CONST (49.0f / 48.0f)

__device__ float g_part[NBLOCKS];
__device__ unsigned g_ticket;   // atomicInc wraps to 0 -> graph-replay safe

__device__ __forceinline__ u64 pack2(float lo, float hi) {
    u64 d; asm("mov.b64 %0, {%1,%2};" : "=l"(d) : "f"(lo), "f"(hi)); return d;
}
__device__ __forceinline__ void unpack2(u64 v, float& lo, float& hi) {
    asm("mov.b64 {%0,%1}, %2;" : "=f"(lo), "=f"(hi) : "l"(v));
}
__device__ __forceinline__ u64 fma2(u64 a, u64 b, u64 c) {
    u64 d; asm("fma.rn.f32x2 %0, %1, %2, %3;" : "=l"(d) : "l"(a), "l"(b), "l"(c)); return d;
}
__device__ __forceinline__ u64 mul2(u64 a, u64 b) {
    u64 d; asm("mul.rn.f32x2 %0, %1, %2;" : "=l"(d) : "l"(a), "l"(b)); return d;
}
__device__ __forceinline__ u64 add2(u64 a, u64 b) {
    u64 d; asm("add.rn.f32x2 %0, %1, %2;" : "=l"(d) : "l"(a), "l"(b)); return d;
}

__global__ __launch_bounds__(256, 3)
void ssim_kernel(const float* __restrict__ X, const float* __restrict__ Y,
                 const float* __restrict__ W, float* __restrict__ out) {
    extern __shared__ u64 sm[];
    u64* sX = sm;
    u64* sY = sm + IN_R * IN_ST;
    u64* sH = sm + 2 * IN_R * IN_ST;   // [32 cols][4 streams x 40 + 2 pad]
    __shared__ float warp_sums[8];
    __shared__ int is_last;

    const int tid = threadIdx.x;
    const int bx = blockIdx.x * TILE_W;
    const int by = blockIdx.y * TILE_H;
    const int n  = blockIdx.z;

    // Separable weights from rank-1 window: u_i = W[i][3]/sqrt(W[3][3])
    u64 wp[7];
    {
        float wc = sqrtf(W[3 * 7 + 3]);
        #pragma unroll
        for (int i = 0; i < 7; i++) {
            float w = W[i * 7 + 3] / wc;
            wp[i] = pack2(w, w);
        }
    }

    const float* Xn = X + (size_t)n * IMG_H * IMG_W;
    const float* Yn = Y + (size_t)n * IMG_H * IMG_W;

    // ---- Phase 1: load 38 rows x 38 pair-cols; pair p = (col p-3, col p+29) ----
    #pragma unroll
    for (int ii = 0; ii < 6; ii++) {
        int i = tid + ii * 256;
        if (i < IN_R * IN_PC) {
            int r = i / IN_PC;
            int c = i - r * IN_PC;
            int gy = by + r - HALO;
            int cl = bx + c - HALO;
            int cr = cl + 32;
            float xl = 0.f, xr = 0.f, yl = 0.f, yr = 0.f;
            if ((unsigned)gy < (unsigned)IMG_H) {
                const float* xrow = Xn + gy * IMG_W;
                const float* yrow = Yn + gy * IMG_W;
                if ((unsigned)cl < (unsigned)IMG_W) { xl = xrow[cl]; yl = yrow[cl]; }
                if ((unsigned)cr < (unsigned)IMG_W) { xr = xrow[cr]; yr = yrow[cr]; }
            }
            sX[r * IN_ST + c] = pack2(xl, xr);
            sY[r * IN_ST + c] = pack2(yl, yr);
        }
    }
    __syncthreads();

    // ---- Phase 2: horizontal conv. Tasks: 38 rows x 8 groups of 4 pair-cols.
    //      Main 256: r = tid&31, cg = tid>>5. Tail 48: r = 32+(tid>>3), cg = tid&7. ----
    #pragma unroll
    for (int part = 0; part < 2; part++) {
        int r, cg;
        bool active;
        if (part == 0) { r = tid & 31; cg = tid >> 5; active = true; }
        else           { r = 32 + (tid >> 3); cg = tid & 7; active = (tid < 48); }
        if (active) {
            const int c0 = cg * 4;
            const u64* px = sX + r * IN_ST + c0;
            const u64* py = sY + r * IN_ST + c0;
            u64 xw[10], yw[10];
            #pragma unroll
            for (int k = 0; k < 5; k++) {
                ulonglong2 vx = *(const ulonglong2*)(px + 2 * k);
                ulonglong2 vy = *(const ulonglong2*)(py + 2 * k);
                xw[2 * k] = vx.x; xw[2 * k + 1] = vx.y;
                yw[2 * k] = vy.x; yw[2 * k + 1] = vy.y;
            }
            #pragma unroll
            for (int j = 0; j < 4; j++) {
                u64 sx = 0, sy = 0, sxx = 0, syy = 0, sxy = 0;
                #pragma unroll
                for (int k = 0; k < 7; k++) {
                    u64 x = xw[j + k], y = yw[j + k], w = wp[k];
                    sx = fma2(x, w, sx);
                    sy = fma2(y, w, sy);
                    u64 wx = mul2(x, w);
                    u64 wy = mul2(y, w);
                    sxx = fma2(wx, x, sxx);
                    syy = fma2(wy, y, syy);
                    sxy = fma2(wx, y, sxy);
                }
                u64* h = sH + (c0 + j) * HB_COLST + r;
                h[0 * HB_SST] = sx;
                h[1 * HB_SST] = sy;
                h[2 * HB_SST] = add2(sxx, syy);
                h[3 * HB_SST] = sxy;
            }
        }
    }
    __syncthreads();

    // ---- Phase 3: vertical conv + SSIM. Exactly 256 tasks:
    //      c = tid&31 (pair-col), g = tid>>5, output rows 4g..4g+3 (window 10). ----
    const int c  = tid & 31;
    const int r0 = (tid >> 5) * 4;
    const u64* hcol = sH + c * HB_COLST + r0;

    u64 mux[4], muy[4], s23[4], sxyv[4];
    #pragma unroll
    for (int s = 0; s < 4; s++) {
        u64 vw[10];
        #pragma unroll
        for (int k = 0; k < 5; k++) {
            ulonglong2 v = *(const ulonglong2*)(hcol + s * HB_SST + 2 * k);
            vw[2 * k] = v.x; vw[2 * k + 1] = v.y;
        }
        #pragma unroll
        for (int j = 0; j < 4; j++) {
            u64 acc = 0;
            #pragma unroll
            for (int k = 0; k < 7; k++)
                acc = fma2(vw[j + k], wp[k], acc);
            if (s == 0) mux[j] = acc;
            else if (s == 1) muy[j] = acc;
            else if (s == 2) s23[j] = acc;
            else sxyv[j] = acc;
        }
    }

    const u64 C1p  = pack2(C1_CONST, C1_CONST);
    const u64 C2p  = pack2(C2_CONST, C2_CONST);
    const u64 covp = pack2(COV_NORM_CONST, COV_NORM_CONST);
    const u64 negp = pack2(-1.f, -1.f);
    const u64 twop = pack2(2.f, 2.f);

    float facc = 0.f;
    #pragma unroll
    for (int j = 0; j < 4; j++) {
        u64 muxy = mul2(mux[j], muy[j]);
        u64 P    = fma2(mux[j], mux[j], mul2(muy[j], muy[j]));   // mux^2 + muy^2
        u64 ssum = mul2(fma2(P,    negp, s23[j]),  covp);        // sxx + syy
        u64 sxy  = mul2(fma2(muxy, negp, sxyv[j]), covp);
        u64 num = mul2(fma2(twop, muxy, C1p), fma2(twop, sxy, C2p));
        u64 den = mul2(add2(P, C1p), add2(ssum, C2p));
        float nl, nh, dl, dh;
        unpack2(num, nl, nh);
        unpack2(den, dl, dh);
        facc += __fdividef(nl, dl) + __fdividef(nh, dh);
    }

    // ---- Block reduction -> per-block float partial ----
    #pragma unroll
    for (int off = 16; off > 0; off >>= 1)
        facc += __shfl_down_sync(0xffffffffu, facc, off);
    if ((tid & 31) == 0) warp_sums[tid >> 5] = facc;
    __syncthreads();
    if (tid == 0) {
        float bs = 0.f;
        #pragma unroll
        for (int w = 0; w < 8; w++) bs += warp_sums[w];
        int bid = blockIdx.x + GRID_X * (blockIdx.y + GRID_Y * blockIdx.z);
        g_part[bid] = bs;
        __threadfence();
        unsigned ticket = atomicInc(&g_ticket, NBLOCKS - 1);
        is_last = (ticket == NBLOCKS - 1);
    }
    __syncthreads();

    // ---- Last block: deterministic double reduction ----
    if (is_last) {
        __shared__ double dsums[8];
        double s = 0.0;
        for (int i = tid; i < NBLOCKS; i += 256) s += (double)__ldcg(&g_part[i]);
        #pragma unroll
        for (int off = 16; off > 0; off >>= 1)
            s += __shfl_down_sync(0xffffffffu, s, off);
        if ((tid & 31) == 0) dsums[tid >> 5] = s;
        __syncthreads();
        if (tid == 0) {
            double t = 0.0;
            #pragma unroll
            for (int w = 0; w < 8; w++) t += dsums[w];
            double total = (double)N_IMG * IMG_H * IMG_W;
            out[0] = (float)(1.0 - t / total);
        }
    }
}

extern "C" void kernel_launch(void* const* d_in, const int* in_sizes, int n_in,
                              void* d_out, int out_size) {
    const float* X = (const float*)d_in[0];
    const float* Y = (const float*)d_in[1];
    const float* W = (const float*)d_in[2];
    float* out = (float*)d_out;

    size_t smem_bytes = (size_t)SMEM_U64 * sizeof(u64);
    cudaFuncSetAttribute(ssim_kernel, cudaFuncAttributeMaxDynamicSharedMemorySize,
                         (int)smem_bytes);

    dim3 grid(GRID_X, GRID_Y, N_IMG);
    ssim_kernel<<<grid, 256, smem_bytes>>>(X, Y, W, out);
}

// round 6
// speedup vs baseline: 1.5077x; 1.2833x over previous
#include <cuda_runtime.h>
#include <cuda_fp16.h>
#include <cuda_bf16.h>

// SSIM fused single-kernel. X,Y: [64,1,320,320] f32; window [1,1,7,7] rank-1 Gaussian.
// out = 1 - mean(ssim_map).
//
// fp16 conv pyramid: inputs staged as half2 pairs (lo = col c, hi = col c+32),
// both separable conv passes in HFMA2; SSIM formula + reduction in f32.
// Streams: sx=conv(x), sy=conv(y), s23=conv(x^2+y^2), sp=conv(xy), with
// z = x^2+y^2 and p = x*y precomputed once per staged pair.

typedef unsigned int u32;

#define IMG_H 320
#define IMG_W 320
#define N_IMG 64
#define TILE_W 64
#define TILE_H 32
#define HALO 3
#define IN_R   38             // rows incl. halo
#define IN_PC  38             // pair-columns incl. halo
#define IN_ST  44             // sX/sY row stride in half2 (11 odd in 16B units)
#define HB_CST 84             // hbuf col stride in half2 (= 21 x 16B, odd -> no conflicts)
#define SMEM_H2 (2 * IN_R * IN_ST + 2 * 32 * HB_CST)   // 3344 + 5376 = 8720 h2 = 34880 B
#define GRID_X (IMG_W / TILE_W)     // 5
#define GRID_Y (IMG_H / TILE_H)     // 10
#define NBLOCKS (GRID_X * GRID_Y * N_IMG)   // 3200

#define C1_CONST 0.0004f
#define C2_CONST 0.0036f
#define COV_NORM_CONST (49.0f / 48.0f)

__device__ float g_part[NBLOCKS];
__device__ unsigned g_ticket;   // atomicInc wraps to 0 -> graph-replay safe

__device__ __forceinline__ u32 h2u(__half2 h) { return *reinterpret_cast<u32*>(&h); }
__device__ __forceinline__ __half2 u2h(u32 u) { return *reinterpret_cast<__half2*>(&u); }

__global__ __launch_bounds__(256, 4)
void ssim_kernel(const float* __restrict__ X, const float* __restrict__ Y,
                 const float* __restrict__ W, float* __restrict__ out) {
    extern __shared__ __half2 sm[];
    __half2* sX  = sm;                          // [38][44]
    __half2* sY  = sm + IN_R * IN_ST;           // [38][44]
    __half2* hb0 = sm + 2 * IN_R * IN_ST;       // [32 c][42 r][{sx,sy}]
    __half2* hb1 = hb0 + 32 * HB_CST;           // [32 c][42 r][{s23,sp}]
    __shared__ float warp_sums[8];
    __shared__ int is_last;

    const int tid = threadIdx.x;
    const int bx = blockIdx.x * TILE_W;
    const int by = blockIdx.y * TILE_H;
    const int n  = blockIdx.z;

    // Separable weights from rank-1 window: u_i = W[i][3]/sqrt(W[3][3])
    __half2 w2[7];
    {
        float wc = sqrtf(W[3 * 7 + 3]);
        #pragma unroll
        for (int i = 0; i < 7; i++)
            w2[i] = __float2half2_rn(W[i * 7 + 3] / wc);
    }

    const float* Xn = X + (size_t)n * IMG_H * IMG_W;
    const float* Yn = Y + (size_t)n * IMG_H * IMG_W;

    // ---- Phase 1: load 38 rows x 38 pair-cols; pair p = (col p-3, col p+29) ----
    #pragma unroll
    for (int ii = 0; ii < 6; ii++) {
        int i = tid + ii * 256;
        if (i < IN_R * IN_PC) {
            int r = i / IN_PC;
            int c = i - r * IN_PC;
            int gy = by + r - HALO;
            int cl = bx + c - HALO;
            int cr = cl + 32;
            float xl = 0.f, xr = 0.f, yl = 0.f, yr = 0.f;
            if ((unsigned)gy < (unsigned)IMG_H) {
                const float* xrow = Xn + gy * IMG_W;
                const float* yrow = Yn + gy * IMG_W;
                if ((unsigned)cl < (unsigned)IMG_W) { xl = xrow[cl]; yl = yrow[cl]; }
                if ((unsigned)cr < (unsigned)IMG_W) { xr = xrow[cr]; yr = yrow[cr]; }
            }
            sX[r * IN_ST + c] = __floats2half2_rn(xl, xr);
            sY[r * IN_ST + c] = __floats2half2_rn(yl, yr);
        }
    }
    __syncthreads();

    // ---- Phase 2: horizontal conv. 304 tasks = 38 rows x 8 groups of 4 pair-cols.
    //      Main 256: r = tid&31, cg = tid>>5. Tail 48: r = 32+(tid>>3), cg = tid&7. ----
    #pragma unroll
    for (int part = 0; part < 2; part++) {
        int r, cg;
        bool active;
        if (part == 0) { r = tid & 31; cg = tid >> 5; active = true; }
        else           { r = 32 + (tid >> 3); cg = tid & 7; active = (tid < 48); }
        if (active) {
            const int c0 = cg * 4;
            const __half2* px = sX + r * IN_ST + c0;
            const __half2* py = sY + r * IN_ST + c0;
            // window of 10 pairs via 3x LDS.128 (extras in padding, ignored)
            u32 xw[10], yw[10];
            {
                uint4 a = *(const uint4*)(px);
                uint4 b = *(const uint4*)(px + 4);
                uint4 cc = *(const uint4*)(px + 8);
                xw[0]=a.x; xw[1]=a.y; xw[2]=a.z; xw[3]=a.w;
                xw[4]=b.x; xw[5]=b.y; xw[6]=b.z; xw[7]=b.w;
                xw[8]=cc.x; xw[9]=cc.y;
                uint4 d = *(const uint4*)(py);
                uint4 e = *(const uint4*)(py + 4);
                uint4 f = *(const uint4*)(py + 8);
                yw[0]=d.x; yw[1]=d.y; yw[2]=d.z; yw[3]=d.w;
                yw[4]=e.x; yw[5]=e.y; yw[6]=e.z; yw[7]=e.w;
                yw[8]=f.x; yw[9]=f.y;
            }
            // precompute z = x^2+y^2, p = x*y once per pair
            u32 zw[10], pw[10];
            #pragma unroll
            for (int k = 0; k < 10; k++) {
                __half2 x = u2h(xw[k]), y = u2h(yw[k]);
                zw[k] = h2u(__hfma2(x, x, __hmul2(y, y)));
                pw[k] = h2u(__hmul2(x, y));
            }
            #pragma unroll
            for (int j = 0; j < 4; j++) {
                __half2 ax = u2h(0), ay = u2h(0), az = u2h(0), ap = u2h(0);
                #pragma unroll
                for (int k = 0; k < 7; k++) {
                    __half2 w = w2[k];
                    ax = __hfma2(u2h(xw[j + k]), w, ax);
                    ay = __hfma2(u2h(yw[j + k]), w, ay);
                    az = __hfma2(u2h(zw[j + k]), w, az);
                    ap = __hfma2(u2h(pw[j + k]), w, ap);
                }
                int base = (c0 + j) * HB_CST + 2 * r;
                *(uint2*)(hb0 + base) = make_uint2(h2u(ax), h2u(ay));
                *(uint2*)(hb1 + base) = make_uint2(h2u(az), h2u(ap));
            }
        }
    }
    __syncthreads();

    // ---- Phase 3: vertical conv (HFMA2) + SSIM (f32). 256 tasks:
    //      c = tid&31, g = tid>>5, output rows 4g..4g+3 (window 10 rows). ----
    const int c  = tid & 31;
    const int r0 = (tid >> 5) * 4;

    u32 amux[4], amuy[4], as23[4], asp[4];
    #pragma unroll
    for (int buf = 0; buf < 2; buf++) {
        const __half2* hb = (buf == 0) ? hb0 : hb1;
        const uint4* p = (const uint4*)(hb + c * HB_CST + 2 * r0);
        // 5 x LDS.128 -> rows r0..r0+9 of both interleaved streams
        u32 s0w[10], s1w[10];
        #pragma unroll
        for (int k = 0; k < 5; k++) {
            uint4 v = p[k];
            s0w[2 * k] = v.x;     s1w[2 * k] = v.y;
            s0w[2 * k + 1] = v.z; s1w[2 * k + 1] = v.w;
        }
        #pragma unroll
        for (int j = 0; j < 4; j++) {
            __half2 a0 = u2h(0), a1 = u2h(0);
            #pragma unroll
            for (int k = 0; k < 7; k++) {
                __half2 w = w2[k];
                a0 = __hfma2(u2h(s0w[j + k]), w, a0);
                a1 = __hfma2(u2h(s1w[j + k]), w, a1);
            }
            if (buf == 0) { amux[j] = h2u(a0); amuy[j] = h2u(a1); }
            else          { as23[j] = h2u(a0); asp[j]  = h2u(a1); }
        }
    }

    float facc = 0.f;
    #pragma unroll
    for (int j = 0; j < 4; j++) {
        float2 mux2f = __half22float2(u2h(amux[j]));
        float2 muy2f = __half22float2(u2h(amuy[j]));
        float2 s23f  = __half22float2(u2h(as23[j]));
        float2 spf   = __half22float2(u2h(asp[j]));
        #pragma unroll
        for (int h = 0; h < 2; h++) {
            float mux = (h == 0) ? mux2f.x : mux2f.y;
            float muy = (h == 0) ? muy2f.x : muy2f.y;
            float s23 = (h == 0) ? s23f.x  : s23f.y;
            float sp  = (h == 0) ? spf.x   : spf.y;
            float muxy = mux * muy;
            float P    = fmaf(mux, mux, muy * muy);
            float ssum = (s23 - P)   * COV_NORM_CONST;
            float sxy  = (sp  - muxy) * COV_NORM_CONST;
            float num = fmaf(2.f, muxy, C1_CONST) * fmaf(2.f, sxy, C2_CONST);
            float den = (P + C1_CONST) * (ssum + C2_CONST);
            facc += __fdividef(num, den);
        }
    }

    // ---- Block reduction -> per-block float partial ----
    #pragma unroll
    for (int off = 16; off > 0; off >>= 1)
        facc += __shfl_down_sync(0xffffffffu, facc, off);
    if ((tid & 31) == 0) warp_sums[tid >> 5] = facc;
    __syncthreads();
    if (tid == 0) {
        float bs = 0.f;
        #pragma unroll
        for (int w = 0; w < 8; w++) bs += warp_sums[w];
        int bid = blockIdx.x + GRID_X * (blockIdx.y + GRID_Y * blockIdx.z);
        g_part[bid] = bs;
        __threadfence();
        unsigned ticket = atomicInc(&g_ticket, NBLOCKS - 1);
        is_last = (ticket == NBLOCKS - 1);
    }
    __syncthreads();

    // ---- Last block: deterministic double reduction ----
    if (is_last) {
        __shared__ double dsums[8];
        double s = 0.0;
        for (int i = tid; i < NBLOCKS; i += 256) s += (double)__ldcg(&g_part[i]);
        #pragma unroll
        for (int off = 16; off > 0; off >>= 1)
            s += __shfl_down_sync(0xffffffffu, s, off);
        if ((tid & 31) == 0) dsums[tid >> 5] = s;
        __syncthreads();
        if (tid == 0) {
            double t = 0.0;
            #pragma unroll
            for (int w = 0; w < 8; w++) t += dsums[w];
            double total = (double)N_IMG * IMG_H * IMG_W;
            out[0] = (float)(1.0 - t / total);
        }
    }
}

extern "C" void kernel_launch(void* const* d_in, const int* in_sizes, int n_in,
                              void* d_out, int out_size) {
    const float* X = (const float*)d_in[0];
    const float* Y = (const float*)d_in[1];
    const float* W = (const float*)d_in[2];
    float* out = (float*)d_out;

    size_t smem_bytes = (size_t)SMEM_H2 * sizeof(__half2);   // 34880 B
    cudaFuncSetAttribute(ssim_kernel, cudaFuncAttributeMaxDynamicSharedMemorySize,
                         (int)smem_bytes);

    dim3 grid(GRID_X, GRID_Y, N_IMG);
    ssim_kernel<<<grid, 256, smem_bytes>>>(X, Y, W, out);
}

// round 7
// speedup vs baseline: 1.5701x; 1.0414x over previous
#include <cuda_runtime.h>
#include <cuda_fp16.h>
#include <cuda_bf16.h>

// SSIM fused single-kernel. X,Y: [64,1,320,320] f32; window [1,1,7,7] rank-1 Gaussian.
// out = 1 - mean(ssim_map).
//
// fp16 conv pyramid on CENTERED data (x' = x - 0.5): variance/covariance are
// shift-invariant, so the E[x^2]-mu^2 cancellation nearly vanishes and fp16
// quantization error halves. SSIM formula + reduction in f32 (mu = mu' + 0.5).
// Streams: conv(x'), conv(y'), conv(x'^2+y'^2), conv(x'y').

typedef unsigned int u32;

#define IMG_H 320
#define IMG_W 320
#define N_IMG 64
#define TILE_W 64
#define TILE_H 32
#define HALO 3
#define IN_R   38             // rows incl. halo
#define IN_PC  38             // pair-columns incl. halo
#define IN_ST  44             // sX/sY row stride in half2 (11 odd in 16B units)
#define HB_CST 84             // hbuf col stride in half2 (21 x 16B, odd -> conflict-free)
#define SMEM_H2 (2 * IN_R * IN_ST + 2 * 32 * HB_CST)   // 8720 h2 = 34880 B
#define GRID_X (IMG_W / TILE_W)     // 5
#define GRID_Y (IMG_H / TILE_H)     // 10
#define NBLOCKS (GRID_X * GRID_Y * N_IMG)   // 3200

#define C1_CONST 0.0004f
#define C2_CONST 0.0036f
#define COV_NORM_CONST (49.0f / 48.0f)

__device__ float g_part[NBLOCKS];
__device__ unsigned g_ticket;   // atomicInc wraps to 0 -> graph-replay safe

__device__ __forceinline__ u32 h2u(__half2 h) { return *reinterpret_cast<u32*>(&h); }
__device__ __forceinline__ __half2 u2h(u32 u) { return *reinterpret_cast<__half2*>(&u); }

__global__ __launch_bounds__(256, 5)
void ssim_kernel(const float* __restrict__ X, const float* __restrict__ Y,
                 const float* __restrict__ W, float* __restrict__ out) {
    extern __shared__ __half2 sm[];
    __half2* sX  = sm;                          // [38][44]
    __half2* sY  = sm + IN_R * IN_ST;           // [38][44]
    __half2* hb0 = sm + 2 * IN_R * IN_ST;       // [32 c][42 r][{sx,sy}]
    __half2* hb1 = hb0 + 32 * HB_CST;           // [32 c][42 r][{s23,sp}]
    __shared__ float warp_sums[8];
    __shared__ int is_last;

    const int tid = threadIdx.x;
    const int bx = blockIdx.x * TILE_W;
    const int by = blockIdx.y * TILE_H;
    const int n  = blockIdx.z;

    // Separable weights from rank-1 window: u_i = W[i][3]/sqrt(W[3][3])
    __half2 w2[7];
    {
        float wc = sqrtf(W[3 * 7 + 3]);
        #pragma unroll
        for (int i = 0; i < 7; i++)
            w2[i] = __float2half2_rn(W[i * 7 + 3] / wc);
    }

    const float* Xn = X + (size_t)n * IMG_H * IMG_W;
    const float* Yn = Y + (size_t)n * IMG_H * IMG_W;

    // ---- Phase 1: load 38 rows x 38 pair-cols, centered; zero-pad = -0.5 ? NO:
    //      padding must stay 0 in ORIGINAL domain -> centered pad value is -0.5. ----
    #pragma unroll
    for (int ii = 0; ii < 6; ii++) {
        int i = tid + ii * 256;
        if (i < IN_R * IN_PC) {
            int r = i / IN_PC;
            int c = i - r * IN_PC;
            int gy = by + r - HALO;
            int cl = bx + c - HALO;
            int cr = cl + 32;
            float xl = 0.f, xr = 0.f, yl = 0.f, yr = 0.f;
            if ((unsigned)gy < (unsigned)IMG_H) {
                const float* xrow = Xn + gy * IMG_W;
                const float* yrow = Yn + gy * IMG_W;
                if ((unsigned)cl < (unsigned)IMG_W) { xl = xrow[cl]; yl = yrow[cl]; }
                if ((unsigned)cr < (unsigned)IMG_W) { xr = xrow[cr]; yr = yrow[cr]; }
            }
            // center: x' = x - 0.5. Out-of-bounds ORIGINAL value is 0 -> x' = -0.5.
            sX[r * IN_ST + c] = __floats2half2_rn(xl - 0.5f, xr - 0.5f);
            sY[r * IN_ST + c] = __floats2half2_rn(yl - 0.5f, yr - 0.5f);
        }
    }
    __syncthreads();

    // ---- Phase 2: horizontal conv. 304 tasks = 38 rows x 8 groups of 4 pair-cols. ----
    #pragma unroll
    for (int part = 0; part < 2; part++) {
        int r, cg;
        bool active;
        if (part == 0) { r = tid & 31; cg = tid >> 5; active = true; }
        else           { r = 32 + (tid >> 3); cg = tid & 7; active = (tid < 48); }
        if (active) {
            const int c0 = cg * 4;
            const __half2* px = sX + r * IN_ST + c0;
            const __half2* py = sY + r * IN_ST + c0;
            u32 xw[10], yw[10];
            {
                uint4 a = *(const uint4*)(px);
                uint4 b = *(const uint4*)(px + 4);
                uint4 cc = *(const uint4*)(px + 8);
                xw[0]=a.x; xw[1]=a.y; xw[2]=a.z; xw[3]=a.w;
                xw[4]=b.x; xw[5]=b.y; xw[6]=b.z; xw[7]=b.w;
                xw[8]=cc.x; xw[9]=cc.y;
                uint4 d = *(const uint4*)(py);
                uint4 e = *(const uint4*)(py + 4);
                uint4 f = *(const uint4*)(py + 8);
                yw[0]=d.x; yw[1]=d.y; yw[2]=d.z; yw[3]=d.w;
                yw[4]=e.x; yw[5]=e.y; yw[6]=e.z; yw[7]=e.w;
                yw[8]=f.x; yw[9]=f.y;
            }
            u32 zw[10], pw[10];
            #pragma unroll
            for (int k = 0; k < 10; k++) {
                __half2 x = u2h(xw[k]), y = u2h(yw[k]);
                zw[k] = h2u(__hfma2(x, x, __hmul2(y, y)));
                pw[k] = h2u(__hmul2(x, y));
            }
            #pragma unroll
            for (int j = 0; j < 4; j++) {
                __half2 ax = u2h(0), ay = u2h(0), az = u2h(0), ap = u2h(0);
                #pragma unroll
                for (int k = 0; k < 7; k++) {
                    __half2 w = w2[k];
                    ax = __hfma2(u2h(xw[j + k]), w, ax);
                    ay = __hfma2(u2h(yw[j + k]), w, ay);
                    az = __hfma2(u2h(zw[j + k]), w, az);
                    ap = __hfma2(u2h(pw[j + k]), w, ap);
                }
                int base = (c0 + j) * HB_CST + 2 * r;
                *(uint2*)(hb0 + base) = make_uint2(h2u(ax), h2u(ay));
                *(uint2*)(hb1 + base) = make_uint2(h2u(az), h2u(ap));
            }
        }
    }
    __syncthreads();

    // ---- Phase 3: vertical conv (HFMA2) + SSIM (f32, de-centered). ----
    const int c  = tid & 31;
    const int r0 = (tid >> 5) * 4;

    u32 amux[4], amuy[4], as23[4], asp[4];
    #pragma unroll
    for (int buf = 0; buf < 2; buf++) {
        const __half2* hb = (buf == 0) ? hb0 : hb1;
        const uint4* p = (const uint4*)(hb + c * HB_CST + 2 * r0);
        u32 s0w[10], s1w[10];
        #pragma unroll
        for (int k = 0; k < 5; k++) {
            uint4 v = p[k];
            s0w[2 * k] = v.x;     s1w[2 * k] = v.y;
            s0w[2 * k + 1] = v.z; s1w[2 * k + 1] = v.w;
        }
        #pragma unroll
        for (int j = 0; j < 4; j++) {
            __half2 a0 = u2h(0), a1 = u2h(0);
            #pragma unroll
            for (int k = 0; k < 7; k++) {
                __half2 w = w2[k];
                a0 = __hfma2(u2h(s0w[j + k]), w, a0);
                a1 = __hfma2(u2h(s1w[j + k]), w, a1);
            }
            if (buf == 0) { amux[j] = h2u(a0); amuy[j] = h2u(a1); }
            else          { as23[j] = h2u(a0); asp[j]  = h2u(a1); }
        }
    }

    float facc = 0.f;
    #pragma unroll
    for (int j = 0; j < 4; j++) {
        float2 muxc2 = __half22float2(u2h(amux[j]));   // centered mu_x'
        float2 muyc2 = __half22float2(u2h(amuy[j]));
        float2 s23c2 = __half22float2(u2h(as23[j]));   // E'[x'^2 + y'^2]
        float2 spc2  = __half22float2(u2h(asp[j]));    // E'[x'y']
        #pragma unroll
        for (int h = 0; h < 2; h++) {
            float muxc = (h == 0) ? muxc2.x : muxc2.y;
            float muyc = (h == 0) ? muyc2.x : muyc2.y;
            float s23c = (h == 0) ? s23c2.x : s23c2.y;
            float spc  = (h == 0) ? spc2.x  : spc2.y;
            // shift-invariant moments
            float Pc   = fmaf(muxc, muxc, muyc * muyc);
            float ssum = (s23c - Pc)          * COV_NORM_CONST;   // sxx + syy
            float sxy  = (spc  - muxc * muyc) * COV_NORM_CONST;
            // de-centered means
            float mux = muxc + 0.5f;
            float muy = muyc + 0.5f;
            float muxy = mux * muy;
            float P    = fmaf(mux, mux, muy * muy);
            float num = fmaf(2.f, muxy, C1_CONST) * fmaf(2.f, sxy, C2_CONST);
            float den = (P + C1_CONST) * (ssum + C2_CONST);
            facc += __fdividef(num, den);
        }
    }

    // ---- Block reduction -> per-block float partial ----
    #pragma unroll
    for (int off = 16; off > 0; off >>= 1)
        facc += __shfl_down_sync(0xffffffffu, facc, off);
    if ((tid & 31) == 0) warp_sums[tid >> 5] = facc;
    __syncthreads();
    if (tid == 0) {
        float bs = 0.f;
        #pragma unroll
        for (int w = 0; w < 8; w++) bs += warp_sums[w];
        int bid = blockIdx.x + GRID_X * (blockIdx.y + GRID_Y * blockIdx.z);
        g_part[bid] = bs;
        __threadfence();
        unsigned ticket = atomicInc(&g_ticket, NBLOCKS - 1);
        is_last = (ticket == NBLOCKS - 1);
    }
    __syncthreads();

    // ---- Last block: deterministic double reduction ----
    if (is_last) {
        __shared__ double dsums[8];
        double s = 0.0;
        for (int i = tid; i < NBLOCKS; i += 256) s += (double)__ldcg(&g_part[i]);
        #pragma unroll
        for (int off = 16; off > 0; off >>= 1)
            s += __shfl_down_sync(0xffffffffu, s, off);
        if ((tid & 31) == 0) dsums[tid >> 5] = s;
        __syncthreads();
        if (tid == 0) {
            double t = 0.0;
            #pragma unroll
            for (int w = 0; w < 8; w++) t += dsums[w];
            double total = (double)N_IMG * IMG_H * IMG_W;
            out[0] = (float)(1.0 - t / total);
        }
    }
}

extern "C" void kernel_launch(void* const* d_in, const int* in_sizes, int n_in,
                              void* d_out, int out_size) {
    const float* X = (const float*)d_in[0];
    const float* Y = (const float*)d_in[1];
    const float* W = (const float*)d_in[2];
    float* out = (float*)d_out;

    size_t smem_bytes = (size_t)SMEM_H2 * sizeof(__half2);   // 34880 B
    cudaFuncSetAttribute(ssim_kernel, cudaFuncAttributeMaxDynamicSharedMemorySize,
                         (int)smem_bytes);

    dim3 grid(GRID_X, GRID_Y, N_IMG);
    ssim_kernel<<<grid, 256, smem_bytes>>>(X, Y, W, out);
}

// round 8
// speedup vs baseline: 1.7558x; 1.1183x over previous
#include <cuda_runtime.h>
#include <cuda_fp16.h>
#include <cuda_bf16.h>

// SSIM fused single-kernel. X,Y: [64,1,320,320] f32; window [1,1,7,7] rank-1 Gaussian.
// out = 1 - mean(ssim_map).
//
// fp16 conv pyramid on CENTERED data (x' = x - 0.5); SSIM formula + reduction f32.
// Staging pair index c (0..39) <-> original cols (bx-4+c, bx+28+c) so all gmem
// loads are aligned float4 (OOB float4s are entirely OOB since 320 % 4 == 0).

typedef unsigned int u32;

#define IMG_H 320
#define IMG_W 320
#define N_IMG 64
#define TILE_W 64
#define TILE_H 32
#define HALO 3
#define IN_R   38             // rows incl. halo
#define IN_PG  10             // float4 groups per row per half (40 pair-cols)
#define IN_ST  44             // staging row stride in half2 (11 x 16B, odd)
#define HB_CST 84             // hbuf col stride in half2 (21 x 16B, odd)
#define SMEM_H2 (2 * IN_R * IN_ST + 2 * 32 * HB_CST)   // 8720 h2 = 34880 B
#define GRID_X (IMG_W / TILE_W)     // 5
#define GRID_Y (IMG_H / TILE_H)     // 10
#define NBLOCKS (GRID_X * GRID_Y * N_IMG)   // 3200

#define C1_CONST 0.0004f
#define C2_CONST 0.0036f
#define COV_NORM_CONST (49.0f / 48.0f)

__device__ float g_part[NBLOCKS];
__device__ unsigned g_ticket;   // atomicInc wraps to 0 -> graph-replay safe

__device__ __forceinline__ u32 h2u(__half2 h) { return *reinterpret_cast<u32*>(&h); }
__device__ __forceinline__ __half2 u2h(u32 u) { return *reinterpret_cast<__half2*>(&u); }

__global__ __launch_bounds__(256, 6)
void ssim_kernel(const float* __restrict__ X, const float* __restrict__ Y,
                 const float* __restrict__ W, float* __restrict__ out) {
    extern __shared__ __half2 sm[];
    __half2* sX  = sm;                          // [38][44] pairs, idx c: cols (bx-4+c, bx+28+c)
    __half2* sY  = sm + IN_R * IN_ST;
    __half2* hb0 = sm + 2 * IN_R * IN_ST;       // [32 c][42 r][{sx,sy}]
    __half2* hb1 = hb0 + 32 * HB_CST;           // [32 c][42 r][{s23,sp}]
    __shared__ float warp_sums[8];
    __shared__ int is_last;

    const int tid = threadIdx.x;
    const int bx = blockIdx.x * TILE_W;
    const int by = blockIdx.y * TILE_H;
    const int n  = blockIdx.z;

    // Separable weights from rank-1 window: u_i = W[i][3]/sqrt(W[3][3])
    __half2 w2[7];
    {
        float wc = sqrtf(W[3 * 7 + 3]);
        #pragma unroll
        for (int i = 0; i < 7; i++)
            w2[i] = __float2half2_rn(W[i * 7 + 3] / wc);
    }

    const float* Xn = X + (size_t)n * IMG_H * IMG_W;
    const float* Yn = Y + (size_t)n * IMG_H * IMG_W;

    // ---- Phase 1: 380 tasks = 38 rows x 10 float4-groups. Each task loads
    //      left f4 @ col bx-4+4g, right f4 @ col bx+28+4g for X and Y,
    //      packs 4 centered half2 pairs per image (one STS.128 each). ----
    const float4 zero4 = make_float4(0.f, 0.f, 0.f, 0.f);
    #pragma unroll
    for (int ii = 0; ii < 2; ii++) {
        int t = tid + ii * 256;
        if (t < IN_R * IN_PG) {
            int r = t / IN_PG;
            int g = t - r * IN_PG;
            int gy = by + r - HALO;
            int lc = bx - 4 + 4 * g;    // left f4 start col
            int rc = bx + 28 + 4 * g;   // right f4 start col
            float4 xl = zero4, xr = zero4, yl = zero4, yr = zero4;
            if ((unsigned)gy < (unsigned)IMG_H) {
                const float* xrow = Xn + gy * IMG_W;
                const float* yrow = Yn + gy * IMG_W;
                if ((unsigned)lc < (unsigned)IMG_W) {   // f4 fully in or fully out
                    xl = *(const float4*)(xrow + lc);
                    yl = *(const float4*)(yrow + lc);
                }
                if ((unsigned)rc < (unsigned)IMG_W) {
                    xr = *(const float4*)(xrow + rc);
                    yr = *(const float4*)(yrow + rc);
                }
            }
            __half2* px = sX + r * IN_ST + 4 * g;
            __half2* py = sY + r * IN_ST + 4 * g;
            uint4 vx, vy;
            vx.x = h2u(__floats2half2_rn(xl.x - 0.5f, xr.x - 0.5f));
            vx.y = h2u(__floats2half2_rn(xl.y - 0.5f, xr.y - 0.5f));
            vx.z = h2u(__floats2half2_rn(xl.z - 0.5f, xr.z - 0.5f));
            vx.w = h2u(__floats2half2_rn(xl.w - 0.5f, xr.w - 0.5f));
            vy.x = h2u(__floats2half2_rn(yl.x - 0.5f, yr.x - 0.5f));
            vy.y = h2u(__floats2half2_rn(yl.y - 0.5f, yr.y - 0.5f));
            vy.z = h2u(__floats2half2_rn(yl.z - 0.5f, yr.z - 0.5f));
            vy.w = h2u(__floats2half2_rn(yl.w - 0.5f, yr.w - 0.5f));
            *(uint4*)px = vx;
            *(uint4*)py = vy;
        }
    }
    __syncthreads();

    // ---- Phase 2: horizontal conv. 304 tasks = 38 rows x 8 groups of 4 out-cols.
    //      Output col j needs staging pairs c0+1+j .. c0+7+j  (c0 = cg*4). ----
    #pragma unroll
    for (int part = 0; part < 2; part++) {
        int r, cg;
        bool active;
        if (part == 0) { r = tid & 31; cg = tid >> 5; active = true; }
        else           { r = 32 + (tid >> 3); cg = tid & 7; active = (tid < 48); }
        if (active) {
            const int c0 = cg * 4;
            const __half2* px = sX + r * IN_ST + c0;
            const __half2* py = sY + r * IN_ST + c0;
            // load 12, use [1..10]
            u32 xw[12], yw[12];
            {
                uint4 a = *(const uint4*)(px);
                uint4 b = *(const uint4*)(px + 4);
                uint4 cc = *(const uint4*)(px + 8);
                xw[0]=a.x; xw[1]=a.y; xw[2]=a.z; xw[3]=a.w;
                xw[4]=b.x; xw[5]=b.y; xw[6]=b.z; xw[7]=b.w;
                xw[8]=cc.x; xw[9]=cc.y; xw[10]=cc.z; xw[11]=cc.w;
                uint4 d = *(const uint4*)(py);
                uint4 e = *(const uint4*)(py + 4);
                uint4 f = *(const uint4*)(py + 8);
                yw[0]=d.x; yw[1]=d.y; yw[2]=d.z; yw[3]=d.w;
                yw[4]=e.x; yw[5]=e.y; yw[6]=e.z; yw[7]=e.w;
                yw[8]=f.x; yw[9]=f.y; yw[10]=f.z; yw[11]=f.w;
            }
            u32 zw[10], pw[10];
            #pragma unroll
            for (int k = 0; k < 10; k++) {
                __half2 x = u2h(xw[k + 1]), y = u2h(yw[k + 1]);
                zw[k] = h2u(__hfma2(x, x, __hmul2(y, y)));
                pw[k] = h2u(__hmul2(x, y));
            }
            #pragma unroll
            for (int j = 0; j < 4; j++) {
                __half2 ax = u2h(0), ay = u2h(0), az = u2h(0), ap = u2h(0);
                #pragma unroll
                for (int k = 0; k < 7; k++) {
                    __half2 w = w2[k];
                    ax = __hfma2(u2h(xw[j + k + 1]), w, ax);
                    ay = __hfma2(u2h(yw[j + k + 1]), w, ay);
                    az = __hfma2(u2h(zw[j + k]), w, az);
                    ap = __hfma2(u2h(pw[j + k]), w, ap);
                }
                int base = (c0 + j) * HB_CST + 2 * r;
                *(uint2*)(hb0 + base) = make_uint2(h2u(ax), h2u(ay));
                *(uint2*)(hb1 + base) = make_uint2(h2u(az), h2u(ap));
            }
        }
    }
    __syncthreads();

    // ---- Phase 3: vertical conv (HFMA2) + SSIM (f32, de-centered). ----
    const int c  = tid & 31;
    const int r0 = (tid >> 5) * 4;

    u32 amux[4], amuy[4], as23[4], asp[4];
    #pragma unroll
    for (int buf = 0; buf < 2; buf++) {
        const __half2* hb = (buf == 0) ? hb0 : hb1;
        const uint4* p = (const uint4*)(hb + c * HB_CST + 2 * r0);
        u32 s0w[10], s1w[10];
        #pragma unroll
        for (int k = 0; k < 5; k++) {
            uint4 v = p[k];
            s0w[2 * k] = v.x;     s1w[2 * k] = v.y;
            s0w[2 * k + 1] = v.z; s1w[2 * k + 1] = v.w;
        }
        #pragma unroll
        for (int j = 0; j < 4; j++) {
            __half2 a0 = u2h(0), a1 = u2h(0);
            #pragma unroll
            for (int k = 0; k < 7; k++) {
                __half2 w = w2[k];
                a0 = __hfma2(u2h(s0w[j + k]), w, a0);
                a1 = __hfma2(u2h(s1w[j + k]), w, a1);
            }
            if (buf == 0) { amux[j] = h2u(a0); amuy[j] = h2u(a1); }
            else          { as23[j] = h2u(a0); asp[j]  = h2u(a1); }
        }
    }

    float facc = 0.f;
    #pragma unroll
    for (int j = 0; j < 4; j++) {
        float2 muxc2 = __half22float2(u2h(amux[j]));
        float2 muyc2 = __half22float2(u2h(amuy[j]));
        float2 s23c2 = __half22float2(u2h(as23[j]));
        float2 spc2  = __half22float2(u2h(asp[j]));
        #pragma unroll
        for (int h = 0; h < 2; h++) {
            float muxc = (h == 0) ? muxc2.x : muxc2.y;
            float muyc = (h == 0) ? muyc2.x : muyc2.y;
            float s23c = (h == 0) ? s23c2.x : s23c2.y;
            float spc  = (h == 0) ? spc2.x  : spc2.y;
            float Pc   = fmaf(muxc, muxc, muyc * muyc);
            float ssum = (s23c - Pc)          * COV_NORM_CONST;
            float sxy  = (spc  - muxc * muyc) * COV_NORM_CONST;
            float mux = muxc + 0.5f;
            float muy = muyc + 0.5f;
            float muxy = mux * muy;
            float P    = fmaf(mux, mux, muy * muy);
            float num = fmaf(2.f, muxy, C1_CONST) * fmaf(2.f, sxy, C2_CONST);
            float den = (P + C1_CONST) * (ssum + C2_CONST);
            facc += __fdividef(num, den);
        }
    }

    // ---- Block reduction -> per-block float partial ----
    #pragma unroll
    for (int off = 16; off > 0; off >>= 1)
        facc += __shfl_down_sync(0xffffffffu, facc, off);
    if ((tid & 31) == 0) warp_sums[tid >> 5] = facc;
    __syncthreads();
    if (tid == 0) {
        float bs = 0.f;
        #pragma unroll
        for (int w = 0; w < 8; w++) bs += warp_sums[w];
        int bid = blockIdx.x + GRID_X * (blockIdx.y + GRID_Y * blockIdx.z);
        g_part[bid] = bs;
        __threadfence();
        unsigned ticket = atomicInc(&g_ticket, NBLOCKS - 1);
        is_last = (ticket == NBLOCKS - 1);
    }
    __syncthreads();

    // ---- Last block: deterministic double reduction ----
    if (is_last) {
        __shared__ double dsums[8];
        double s = 0.0;
        for (int i = tid; i < NBLOCKS; i += 256) s += (double)__ldcg(&g_part[i]);
        #pragma unroll
        for (int off = 16; off > 0; off >>= 1)
            s += __shfl_down_sync(0xffffffffu, s, off);
        if ((tid & 31) == 0) dsums[tid >> 5] = s;
        __syncthreads();
        if (tid == 0) {
            double t = 0.0;
            #pragma unroll
            for (int w = 0; w < 8; w++) t += dsums[w];
            double total = (double)N_IMG * IMG_H * IMG_W;
            out[0] = (float)(1.0 - t / total);
        }
    }
}

extern "C" void kernel_launch(void* const* d_in, const int* in_sizes, int n_in,
                              void* d_out, int out_size) {
    const float* X = (const float*)d_in[0];
    const float* Y = (const float*)d_in[1];
    const float* W = (const float*)d_in[2];
    float* out = (float*)d_out;

    size_t smem_bytes = (size_t)SMEM_H2 * sizeof(__half2);   // 34880 B
    cudaFuncSetAttribute(ssim_kernel, cudaFuncAttributeMaxDynamicSharedMemorySize,
                         (int)smem_bytes);

    dim3 grid(GRID_X, GRID_Y, N_IMG);
    ssim_kernel<<<grid, 256, smem_bytes>>>(X, Y, W, out);
}